// round 7
// baseline (speedup 1.0000x reference)
#include <cuda_runtime.h>
#include <cuda_bf16.h>

#define NC    35
#define TPB   128
#define TILE  128
#define NSLOT 3

#define SMEM_BYTES (NSLOT * TILE * (NC * 4 + 8))   // 56832

__device__ unsigned g_ctr  = 0;
__device__ unsigned g_done = 0;
__device__ float    g_acc  = 0.f;

__device__ __forceinline__ void cp_async16(void* dst, const void* src) {
    unsigned s = (unsigned)__cvta_generic_to_shared(dst);
    asm volatile("cp.async.cg.shared.global [%0], [%1], 16;" :: "r"(s), "l"(src) : "memory");
}
__device__ __forceinline__ void cp_async4(void* dst, const void* src) {
    unsigned s = (unsigned)__cvta_generic_to_shared(dst);
    asm volatile("cp.async.ca.shared.global [%0], [%1], 4;" :: "r"(s), "l"(src) : "memory");
}
#define CP_COMMIT()  asm volatile("cp.async.commit_group;" ::: "memory")
#define CP_WAIT(n)   asm volatile("cp.async.wait_group %0;" :: "n"(n) : "memory")

__global__ __launch_bounds__(TPB) void fll_loss_kernel(
    const float* __restrict__ logits,
    const int* __restrict__ targets,
    const int* __restrict__ turns,
    float* __restrict__ out,
    int B, float invB)
{
    extern __shared__ float dyn[];
    float* sl = dyn;                                   // NSLOT * TILE * NC floats
    int*   st = (int*)(dyn + NSLOT * TILE * NC);       // NSLOT * TILE targets
    int*   su = st + NSLOT * TILE;                     // NSLOT * TILE turns

    __shared__ int s_tk[2];   // ping-pong stolen-ticket mailbox
    __shared__ int s_base;

    const int tid    = threadIdx.x;
    const int ntiles = (B + TILE - 1) / TILE;

    auto prefetch = [&](int tile, int slot) {
        const int row0 = tile * TILE;
        const int rows = min(TILE, B - row0);
        float* sll = sl + slot * TILE * NC;
        int*   stl = st + slot * TILE;
        int*   sul = su + slot * TILE;
        if (rows == TILE) {
            const float4* src = (const float4*)(logits + (size_t)row0 * NC);
            float4*       dst = (float4*)sll;
            #pragma unroll
            for (int i = tid; i < TILE * NC / 4; i += TPB)    // 1120 x 16B
                cp_async16(dst + i, src + i);
            if (tid < TILE / 4) {
                cp_async16(((int4*)stl) + tid, ((const int4*)(targets + row0)) + tid);
                cp_async16(((int4*)sul) + tid, ((const int4*)(turns   + row0)) + tid);
            }
        } else {   // tail tile
            for (int i = tid; i < rows * NC; i += TPB)
                cp_async4(&sll[i], logits + (size_t)row0 * NC + i);
            for (int i = tid; i < rows; i += TPB) {
                cp_async4(&stl[i], targets + row0 + i);
                cp_async4(&sul[i], turns   + row0 + i);
            }
        }
        CP_COMMIT();
    };

    // ---- prologue: steal 3 tickets in one atomic ----
    if (tid == 0) {
        unsigned r = atomicAdd(&g_ctr, 3u);
        s_base  = (int)r;
        s_tk[0] = (int)r + 2;
    }
    __syncthreads();
    int cur = s_base;
    int nx1 = s_base + 1;
    int npend = 0;
    if (cur < ntiles) { prefetch(cur, 0); npend++; }
    if (nx1 < ntiles) { prefetch(nx1, 1); npend++; }

    float acc = 0.0f;
    int slot = 0, pslot = 2, par = 0;

    while (cur < ntiles) {
        // retire cur's group (in-order completion => cur's data landed)
        if (npend >= 2) { CP_WAIT(1); npend = 1; }
        else            { CP_WAIT(0); npend = 0; }
        __syncthreads();          // cur visible; slot 'pslot' provably free

        const int nx2 = s_tk[par];                         // ticket k+2
        if (tid == 0) s_tk[par ^ 1] = (int)atomicAdd(&g_ctr, 1u);  // steal k+3 (hidden)

        // prefetch BEFORE compute: keep 2 groups in flight during compute
        if (nx2 < ntiles) { prefetch(nx2, pslot); npend++; }

        // ---- compute cur (no max-subtract: logits are O(1)) ----
        const int rows = min(TILE, B - cur * TILE);
        if (tid < rows) {
            const float* row = sl + slot * TILE * NC + tid * NC;  // stride 35
            float s0 = 0.f, s1 = 0.f, s2 = 0.f, s3 = 0.f;
            #pragma unroll
            for (int c = 0; c < NC; c += 4) {
                s0 += __expf(row[c]);
                if (c + 1 < NC) s1 += __expf(row[c + 1]);
                if (c + 2 < NC) s2 += __expf(row[c + 2]);
                if (c + 3 < NC) s3 += __expf(row[c + 3]);
            }
            const float s = (s0 + s1) + (s2 + s3);

            const int   tgt  = st[slot * TILE + tid];
            const float loss = __logf(s) - row[tgt];

            const float t = (float)su[slot * TILE + tid];
            const float w = fminf(fmaxf(0.05f * t + 0.4f, 0.7f), 1.0f);
            acc += w * loss;
        }

        cur = nx1; nx1 = nx2;
        slot  = (slot  + 1 == NSLOT) ? 0 : slot  + 1;
        pslot = (pslot + 1 == NSLOT) ? 0 : pslot + 1;
        par ^= 1;
    }

    // ---- block reduction + last-block-out finish ----
    #pragma unroll
    for (int o = 16; o > 0; o >>= 1)
        acc += __shfl_down_sync(0xffffffffu, acc, o);

    __shared__ float wsum[TPB / 32];
    if ((tid & 31) == 0) wsum[tid >> 5] = acc;
    __syncthreads();

    if (tid == 0) {
        float a = wsum[0];
        #pragma unroll
        for (int wgi = 1; wgi < TPB / 32; wgi++) a += wsum[wgi];

        atomicAdd(&g_acc, a);
        __threadfence();
        const unsigned prev = atomicAdd(&g_done, 1u);
        if (prev == gridDim.x - 1) {
            const float total = atomicExch(&g_acc, 0.0f);
            *out = total * invB;
            g_ctr  = 0;          // self-clean for graph replay
            g_done = 0;
            __threadfence();
        }
    }
}

extern "C" void kernel_launch(void* const* d_in, const int* in_sizes, int n_in,
                              void* d_out, int out_size)
{
    const float* logits  = (const float*)d_in[0];
    const int*   targets = (const int*)d_in[1];
    const int*   turns   = (const int*)d_in[2];
    float* out = (float*)d_out;

    const int B      = in_sizes[1];
    const int ntiles = (B + TILE - 1) / TILE;

    cudaFuncSetAttribute(fll_loss_kernel,
                         cudaFuncAttributeMaxDynamicSharedMemorySize, SMEM_BYTES);

    int grid = 148 * 4;                 // persistent: 4 blocks/SM (56.8KB smem each)
    if (grid > ntiles) grid = ntiles;
    if (grid < 1) grid = 1;

    fll_loss_kernel<<<grid, TPB, SMEM_BYTES>>>(logits, targets, turns, out,
                                               B, 1.0f / (float)B);
}